// round 1
// baseline (speedup 1.0000x reference)
#include <cuda_runtime.h>

// Problem constants
#define N_ROWS   16384            // 32*512 flattened x rows
#define N_CODES  8192
#define DIM      512
#define Q_ELEMS  (N_ROWS * DIM)   // 8388608

// GEMM tiling
#define BM 128
#define BN 128
#define DK 16
#define KSPLIT 8
#define KCHUNK (N_CODES / KSPLIT) // 1024
#define AS_STRIDE 132             // padded row stride (floats)

// -------- scratch (no allocation allowed -> device globals) ------------
__device__ float g_xnorm[N_ROWS];
__device__ float g_enorm[N_CODES];
__device__ float g_pval[N_ROWS * KSPLIT];
__device__ int   g_pidx[N_ROWS * KSPLIT];
__device__ float g_rowsq[N_ROWS];
__device__ int   g_maxidx;

__global__ void init_kernel() { g_maxidx = 0; }

// one warp per row, handles both x and emb norms in one grid
__global__ void norms_kernel(const float* __restrict__ x,
                             const float* __restrict__ emb) {
    int b = blockIdx.x;
    const float* a;
    float* o;
    int row;
    if (b < N_ROWS / 8) {
        a = x; o = g_xnorm; row = b * 8 + (threadIdx.x >> 5);
    } else {
        a = emb; o = g_enorm; row = (b - N_ROWS / 8) * 8 + (threadIdx.x >> 5);
    }
    int lane = threadIdx.x & 31;
    const float4* p = reinterpret_cast<const float4*>(a + (size_t)row * DIM);
    float s = 0.f;
    #pragma unroll
    for (int c = lane; c < DIM / 4; c += 32) {
        float4 v = p[c];
        s += v.x * v.x + v.y * v.y + v.z * v.z + v.w * v.w;
    }
    #pragma unroll
    for (int off = 16; off; off >>= 1) s += __shfl_xor_sync(0xffffffffu, s, off);
    if (lane == 0) o[row] = s;
}

// -------- packed f32x2 helpers ------------------------------------------
__device__ __forceinline__ unsigned long long pack_dup(float v) {
    unsigned long long r;
    asm("mov.b64 %0, {%1, %2};" : "=l"(r) : "f"(v), "f"(v));
    return r;
}
__device__ __forceinline__ void unpack2(unsigned long long v, float& lo, float& hi) {
    asm("mov.b64 {%0, %1}, %2;" : "=f"(lo), "=f"(hi) : "l"(v));
}

// -------- main fused GEMM + argmin ---------------------------------------
// grid (N_ROWS/BM, KSPLIT), block 256.
// Each CTA: rows [bx*128, +128), codes [by*1024, +1024).
__global__ void vq_main_kernel(const float* __restrict__ x,
                               const float* __restrict__ emb) {
    __shared__ __align__(16) float as_[2][DK][AS_STRIDE];
    __shared__ __align__(16) float bs_[2][DK][AS_STRIDE];

    const int tid = threadIdx.x;
    const int tx = tid & 15, ty = tid >> 4;
    const int rowBase = blockIdx.x * BM;
    const int codeBase0 = blockIdx.y * KCHUNK;
    const int m0 = ty * 8, n0 = tx * 8;
    const int lrow = tid >> 2;
    const int lc = (tid & 3) * 4;

    unsigned aBase = (unsigned)__cvta_generic_to_shared(&as_[0][0][0]);
    unsigned bBase = (unsigned)__cvta_generic_to_shared(&bs_[0][0][0]);

    const float4* xg0 = reinterpret_cast<const float4*>(x + (size_t)(rowBase + lrow) * DIM + lc);
    const float4* xg1 = reinterpret_cast<const float4*>(x + (size_t)(rowBase + lrow + 64) * DIM + lc);

    float xn[8];
    #pragma unroll
    for (int i = 0; i < 8; i++) xn[i] = g_xnorm[rowBase + m0 + i];

    float rv[8]; int ri[8];
    #pragma unroll
    for (int i = 0; i < 8; i++) { rv[i] = 3.4028235e38f; ri[i] = 0x7fffffff; }

    for (int kt = 0; kt < KCHUNK / BN; kt++) {
        const int codeBase = codeBase0 + kt * BN;
        const float4* eg0 = reinterpret_cast<const float4*>(emb + (size_t)(codeBase + lrow) * DIM + lc);
        const float4* eg1 = reinterpret_cast<const float4*>(emb + (size_t)(codeBase + lrow + 64) * DIM + lc);

        // packed accumulators: acc[i2][j] = {C[m0+2*i2][n0+j], C[m0+2*i2+1][n0+j]}
        unsigned long long acc[4][8];
        #pragma unroll
        for (int i = 0; i < 4; i++)
            #pragma unroll
            for (int j = 0; j < 8; j++) acc[i][j] = 0ull;

        // preload d-tile 0 into buffer 0 (transposed store: [dk][row])
        {
            float4 rx0 = xg0[0], rx1 = xg1[0], re0 = eg0[0], re1 = eg1[0];
            #pragma unroll
            for (int q = 0; q < 4; q++) {
                as_[0][lc + q][lrow]      = (&rx0.x)[q];
                as_[0][lc + q][lrow + 64] = (&rx1.x)[q];
                bs_[0][lc + q][lrow]      = (&re0.x)[q];
                bs_[0][lc + q][lrow + 64] = (&re1.x)[q];
            }
        }
        __syncthreads();

        int buf = 0;
        for (int ds = 0; ds < DIM / DK; ds++) {
            float4 nx0, nx1, ne0, ne1;
            if (ds < DIM / DK - 1) {
                int off = (ds + 1) * (DK / 4);
                nx0 = xg0[off]; nx1 = xg1[off]; ne0 = eg0[off]; ne1 = eg1[off];
            }
            unsigned aRow = aBase + (unsigned)((buf * DK) * AS_STRIDE + m0) * 4u;
            unsigned bRow = bBase + (unsigned)((buf * DK) * AS_STRIDE + n0) * 4u;
            #pragma unroll
            for (int dk = 0; dk < DK; dk++) {
                unsigned aAddr = aRow + dk * (AS_STRIDE * 4);
                unsigned bAddr = bRow + dk * (AS_STRIDE * 4);
                unsigned long long a2[4];
                asm volatile("ld.shared.v2.u64 {%0, %1}, [%2];"
                             : "=l"(a2[0]), "=l"(a2[1]) : "r"(aAddr));
                asm volatile("ld.shared.v2.u64 {%0, %1}, [%2];"
                             : "=l"(a2[2]), "=l"(a2[3]) : "r"(aAddr + 16));
                float bf[8];
                asm volatile("ld.shared.v4.f32 {%0, %1, %2, %3}, [%4];"
                             : "=f"(bf[0]), "=f"(bf[1]), "=f"(bf[2]), "=f"(bf[3]) : "r"(bAddr));
                asm volatile("ld.shared.v4.f32 {%0, %1, %2, %3}, [%4];"
                             : "=f"(bf[4]), "=f"(bf[5]), "=f"(bf[6]), "=f"(bf[7]) : "r"(bAddr + 16));
                unsigned long long bb[8];
                #pragma unroll
                for (int j = 0; j < 8; j++) bb[j] = pack_dup(bf[j]);
                #pragma unroll
                for (int i = 0; i < 4; i++)
                    #pragma unroll
                    for (int j = 0; j < 8; j++)
                        asm("fma.rn.f32x2 %0, %1, %2, %0;"
                            : "+l"(acc[i][j]) : "l"(a2[i]), "l"(bb[j]));
            }
            if (ds < DIM / DK - 1) {
                int nb = buf ^ 1;
                #pragma unroll
                for (int q = 0; q < 4; q++) {
                    as_[nb][lc + q][lrow]      = (&nx0.x)[q];
                    as_[nb][lc + q][lrow + 64] = (&nx1.x)[q];
                    bs_[nb][lc + q][lrow]      = (&ne0.x)[q];
                    bs_[nb][lc + q][lrow + 64] = (&ne1.x)[q];
                }
            }
            __syncthreads();
            buf ^= 1;
        }

        // ---- epilogue: dist = (xnorm + enorm) - 2*dot, matching reference rounding
        float bestv[8]; int besti[8];
        #pragma unroll
        for (int i = 0; i < 8; i++) { bestv[i] = 3.4028235e38f; besti[i] = 0x7fffffff; }
        #pragma unroll
        for (int j = 0; j < 8; j++) {
            const int idx = codeBase + n0 + j;
            const float env = g_enorm[idx];
            #pragma unroll
            for (int i2 = 0; i2 < 4; i2++) {
                float c0, c1;
                unpack2(acc[i2][j], c0, c1);
                float d0 = __fsub_rn(__fadd_rn(xn[2 * i2], env), 2.0f * c0);
                float d1 = __fsub_rn(__fadd_rn(xn[2 * i2 + 1], env), 2.0f * c1);
                int r0 = 2 * i2, r1 = 2 * i2 + 1;
                if (d0 < bestv[r0] || (d0 == bestv[r0] && idx < besti[r0])) { bestv[r0] = d0; besti[r0] = idx; }
                if (d1 < bestv[r1] || (d1 == bestv[r1] && idx < besti[r1])) { bestv[r1] = d1; besti[r1] = idx; }
            }
        }
        // butterfly min across the 16 tx-lanes (lex order (val, idx) -> first-index ties)
        #pragma unroll
        for (int i = 0; i < 8; i++) {
            float v = bestv[i]; int id = besti[i];
            #pragma unroll
            for (int off = 8; off; off >>= 1) {
                float ov = __shfl_xor_sync(0xffffffffu, v, off);
                int   oi = __shfl_xor_sync(0xffffffffu, id, off);
                if (ov < v || (ov == v && oi < id)) { v = ov; id = oi; }
            }
            if (v < rv[i] || (v == rv[i] && id < ri[i])) { rv[i] = v; ri[i] = id; }
        }
    }

    if (tx == 0) {
        #pragma unroll
        for (int i = 0; i < 8; i++) {
            int r = rowBase + m0 + i;
            g_pval[(size_t)r * KSPLIT + blockIdx.y] = rv[i];
            g_pidx[r * KSPLIT + blockIdx.y] = ri[i];
        }
    }
}

// -------- per-row finalize: reduce KSPLIT partials, gather, straight-through
// out layout: [quantized_st (Q_ELEMS)] [loss] [perplexity] [indices (N_ROWS)]
__global__ void finalize_rows_kernel(const float* __restrict__ x,
                                     const float* __restrict__ emb,
                                     float* __restrict__ out) {
    const int row = blockIdx.x;
    const int tid = threadIdx.x;  // 128 threads
    __shared__ int sidx;
    __shared__ float red[128];

    if (tid == 0) {
        float bv = g_pval[(size_t)row * KSPLIT];
        int   bi = g_pidx[row * KSPLIT];
        #pragma unroll
        for (int c = 1; c < KSPLIT; c++) {
            float v = g_pval[(size_t)row * KSPLIT + c];
            int  ii = g_pidx[row * KSPLIT + c];
            if (v < bv || (v == bv && ii < bi)) { bv = v; bi = ii; }
        }
        sidx = bi;
        out[Q_ELEMS + 2 + row] = (float)bi;
        atomicMax(&g_maxidx, bi);
    }
    __syncthreads();
    const int idx = sidx;

    float ss = 0.f;
    #pragma unroll
    for (int d = tid; d < DIM; d += 128) {
        float q  = emb[(size_t)idx * DIM + d];
        float xv = x[(size_t)row * DIM + d];
        float diff = __fsub_rn(q, xv);
        // straight-through forward value with the reference's exact rounding
        out[(size_t)row * DIM + d] = __fadd_rn(xv, diff);
        ss += diff * diff;
    }
    red[tid] = ss;
    __syncthreads();
    #pragma unroll
    for (int s = 64; s > 0; s >>= 1) {
        if (tid < s) red[tid] += red[tid + s];
        __syncthreads();
    }
    if (tid == 0) g_rowsq[row] = red[0];
}

// -------- scalars: loss + perplexity (deterministic reduction) -----------
__global__ void scalars_kernel(float* __restrict__ out) {
    __shared__ float red[1024];
    const int tid = threadIdx.x;
    float s = 0.f;
    for (int r = tid; r < N_ROWS; r += 1024) s += g_rowsq[r];
    red[tid] = s;
    __syncthreads();
    #pragma unroll
    for (int st = 512; st > 0; st >>= 1) {
        if (tid < st) red[tid] += red[tid + st];
        __syncthreads();
    }
    if (tid == 0) {
        float mean = red[0] / (float)Q_ELEMS;
        out[Q_ELEMS] = 1.25f * mean;  // q_latent + 0.25*e_latent (forward-equal)
        float L = (float)(g_maxidx + 1);
        float avg = 1.0f / L;
        out[Q_ELEMS + 1] = expf(-avg * logf(avg + 1e-10f));
    }
}

extern "C" void kernel_launch(void* const* d_in, const int* in_sizes, int n_in,
                              void* d_out, int out_size) {
    const float* x   = (const float*)d_in[0];
    const float* emb = (const float*)d_in[1];
    float* out = (float*)d_out;

    init_kernel<<<1, 1>>>();
    norms_kernel<<<(N_ROWS / 8) + (N_CODES / 8), 256>>>(x, emb);
    dim3 grid(N_ROWS / BM, KSPLIT);
    vq_main_kernel<<<grid, 256>>>(x, emb);
    finalize_rows_kernel<<<N_ROWS, 128>>>(x, emb, out);
    scalars_kernel<<<1, 1024>>>(out);
}

// round 3
// speedup vs baseline: 7.3534x; 7.3534x over previous
#include <cuda_runtime.h>
#include <cuda_bf16.h>
#include <cstdint>

// ---------------- problem constants ----------------
#define N_ROWS   16384
#define N_CODES  8192
#define DIM      512
#define Q_ELEMS  (N_ROWS * DIM)

// ---------------- GEMM tiling ----------------
#define BM 128
#define BN 128
#define KC 64                 // K elems per stage (bf16) = 128 B per row
#define NSTAGES (DIM / KC)    // 8
#define CH 8                  // codes per argmin chunk
#define NCH (N_CODES / CH)    // 1024 chunk-mins per row
#define EPS 5.0e-4f

// dynamic smem: 2 stages x (A 16KB + B 16KB) = 65536, enorm tile at 65536
#define STG_BYTES 32768
#define SM_BOFF   16384
#define SM_ENORM  65536
#define SM_TOTAL  (65536 + 512)

// ---------------- scratch (device globals; no allocation allowed) ----------------
__device__ __align__(256) __nv_bfloat16 g_hx[(size_t)N_ROWS * DIM];
__device__ __align__(256) __nv_bfloat16 g_he[(size_t)N_CODES * DIM];
__device__ float g_xnorm[N_ROWS];
__device__ float g_enorm[N_CODES];
__device__ float g_cmin[(size_t)N_ROWS * NCH];
__device__ float g_rowsq[N_ROWS];
__device__ int   g_maxidx;

// ---------------- PTX helpers ----------------
__device__ __forceinline__ uint32_t smem_u32(const void* p) {
    uint32_t a;
    asm("{ .reg .u64 t; cvta.to.shared.u64 t, %1; cvt.u32.u64 %0, t; }"
        : "=r"(a) : "l"(p));
    return a;
}
__device__ __forceinline__ void cp16(uint32_t dst, const void* src) {
    asm volatile("cp.async.cg.shared.global [%0], [%1], 16;" :: "r"(dst), "l"(src) : "memory");
}
#define CP_COMMIT() asm volatile("cp.async.commit_group;" ::: "memory")
#define CP_WAIT(n)  asm volatile("cp.async.wait_group %0;" :: "n"(n) : "memory")

#define SWZ(b) ((b) ^ (((b) >> 3) & 0x70))

__device__ __forceinline__ void ldsm4(uint32_t* r, uint32_t addr) {
    asm volatile("ldmatrix.sync.aligned.m8n8.x4.shared.b16 {%0,%1,%2,%3}, [%4];"
                 : "=r"(r[0]), "=r"(r[1]), "=r"(r[2]), "=r"(r[3]) : "r"(addr));
}
__device__ __forceinline__ void mma16816(float* c, const uint32_t* a, const uint32_t* b) {
    asm volatile(
        "mma.sync.aligned.m16n8k16.row.col.f32.bf16.bf16.f32 "
        "{%0,%1,%2,%3}, {%4,%5,%6,%7}, {%8,%9}, {%0,%1,%2,%3};"
        : "+f"(c[0]), "+f"(c[1]), "+f"(c[2]), "+f"(c[3])
        : "r"(a[0]), "r"(a[1]), "r"(a[2]), "r"(a[3]), "r"(b[0]), "r"(b[1]));
}

// ---------------- kernels ----------------
__global__ void init_kernel() { g_maxidx = 0; }

// one warp per row: fp32 norm + bf16 convert
__global__ void convert_kernel(const float* __restrict__ x, const float* __restrict__ emb) {
    int warp = (blockIdx.x * blockDim.x + threadIdx.x) >> 5;
    int lane = threadIdx.x & 31;
    const float* src; __nv_bfloat16* dst; float* nrm; int row;
    if (warp < N_ROWS) { src = x; dst = g_hx; nrm = g_xnorm; row = warp; }
    else               { src = emb; dst = g_he; nrm = g_enorm; row = warp - N_ROWS; }
    const float4* p = reinterpret_cast<const float4*>(src + (size_t)row * DIM);
    uint2* o = reinterpret_cast<uint2*>(dst + (size_t)row * DIM);
    float s = 0.f;
    #pragma unroll
    for (int c = lane; c < DIM / 4; c += 32) {
        float4 v = p[c];
        s += v.x * v.x + v.y * v.y + v.z * v.z + v.w * v.w;
        __nv_bfloat162 lo = __floats2bfloat162_rn(v.x, v.y);
        __nv_bfloat162 hi = __floats2bfloat162_rn(v.z, v.w);
        uint2 u;
        u.x = *reinterpret_cast<unsigned*>(&lo);
        u.y = *reinterpret_cast<unsigned*>(&hi);
        o[c] = u;
    }
    #pragma unroll
    for (int off = 16; off; off >>= 1) s += __shfl_xor_sync(0xffffffffu, s, off);
    if (lane == 0) nrm[row] = s;
}

// fast bf16 HMMA GEMM: per CTA 128 rows x 128 codes x K=512.
// Epilogue: d~ = enorm - 2*dot, per-row min over 8-code chunks -> g_cmin.
__global__ void __launch_bounds__(256, 2) vq_gemm_kernel() {
    extern __shared__ __align__(1024) char smem[];
    const int tid = threadIdx.x;
    const int w = tid >> 5, l = tid & 31;
    const int rowBase = blockIdx.x * BM;
    const int cb = blockIdx.y * BN;
    const uint32_t sb = smem_u32(smem);
    float* senorm = reinterpret_cast<float*>(smem + SM_ENORM);

    if (tid < BN) senorm[tid] = g_enorm[cb + tid];

    // warp layout: 2 (M) x 4 (N); warp tile 64 x 32
    const int m0 = (w >> 2) * 64;
    const int n0 = (w & 3) * 32;

    // ldmatrix lane addressing
    const int aRowLane = l & 15;           // row within 16
    const int aChunkHi = l >> 4;           // +0/+1 16B chunk (k halves)
    const int bRowLane = ((l >> 4) & 1) * 8 + (l & 7);
    const int bChunkHi = (l >> 3) & 1;

    float c[4][4][4];
    #pragma unroll
    for (int mt = 0; mt < 4; mt++)
        #pragma unroll
        for (int nt = 0; nt < 4; nt++)
            #pragma unroll
            for (int e = 0; e < 4; e++) c[mt][nt][e] = 0.f;

    // stage loader: K chunk kc -> stage buffer s
    auto load_stage = [&](int kc, int s) {
        const int kb = kc * KC;
        const uint32_t stg = sb + (uint32_t)s * STG_BYTES;
        #pragma unroll
        for (int q = 0; q < 4; q++) {
            int t = tid + q * 256;
            int r = t >> 3, ch = t & 7;
            cp16(stg + SWZ((uint32_t)(r * 128 + ch * 16)),
                 g_hx + (size_t)(rowBase + r) * DIM + kb + ch * 8);
        }
        #pragma unroll
        for (int q = 0; q < 4; q++) {
            int t = tid + q * 256;
            int r = t >> 3, ch = t & 7;
            cp16(stg + SM_BOFF + SWZ((uint32_t)(r * 128 + ch * 16)),
                 g_he + (size_t)(cb + r) * DIM + kb + ch * 8);
        }
        CP_COMMIT();
    };

    load_stage(0, 0);
    load_stage(1, 1);

    for (int i = 0; i < NSTAGES; i++) {
        if (i < NSTAGES - 1) CP_WAIT(1); else CP_WAIT(0);
        __syncthreads();
        const uint32_t aStg = sb + (uint32_t)(i & 1) * STG_BYTES;
        const uint32_t bStg = aStg + SM_BOFF;
        #pragma unroll
        for (int ks = 0; ks < 4; ks++) {
            uint32_t a[4][4], b[4][2];
            #pragma unroll
            for (int mt = 0; mt < 4; mt++) {
                uint32_t off = (uint32_t)((m0 + mt * 16 + aRowLane) * 128
                                          + (ks * 2 + aChunkHi) * 16);
                ldsm4(a[mt], aStg + SWZ(off));
            }
            #pragma unroll
            for (int nt2 = 0; nt2 < 2; nt2++) {
                uint32_t r4[4];
                uint32_t off = (uint32_t)((n0 + nt2 * 16 + bRowLane) * 128
                                          + (ks * 2 + bChunkHi) * 16);
                ldsm4(r4, bStg + SWZ(off));
                b[nt2 * 2][0] = r4[0]; b[nt2 * 2][1] = r4[1];
                b[nt2 * 2 + 1][0] = r4[2]; b[nt2 * 2 + 1][1] = r4[3];
            }
            #pragma unroll
            for (int mt = 0; mt < 4; mt++)
                #pragma unroll
                for (int nt = 0; nt < 4; nt++)
                    mma16816(c[mt][nt], a[mt], b[nt]);
        }
        __syncthreads();
        if (i + 2 < NSTAGES) load_stage(i + 2, i & 1);
    }

    // ---- epilogue: chunk (8-code) mins -> smem staging -> coalesced gmem
    __syncthreads();   // stage buffers free; reuse as staging [128][20] floats
    float* sbuf = reinterpret_cast<float*>(smem);

    const int j0 = (l & 3) * 2;   // col pair within n8 tile
    #pragma unroll
    for (int mt = 0; mt < 4; mt++) {
        #pragma unroll
        for (int nt = 0; nt < 4; nt++) {
            const int colBase = n0 + nt * 8 + j0;
            float en0 = senorm[colBase], en1 = senorm[colBase + 1];
            float v0 = fminf(en0 - 2.0f * c[mt][nt][0], en1 - 2.0f * c[mt][nt][1]);
            float v1 = fminf(en0 - 2.0f * c[mt][nt][2], en1 - 2.0f * c[mt][nt][3]);
            #pragma unroll
            for (int off = 1; off <= 2; off <<= 1) {
                v0 = fminf(v0, __shfl_xor_sync(0xffffffffu, v0, off));
                v1 = fminf(v1, __shfl_xor_sync(0xffffffffu, v1, off));
            }
            if ((l & 3) == 0) {
                int rloc = m0 + mt * 16 + (l >> 2);
                int chLoc = (w & 3) * 4 + nt;
                sbuf[rloc * 20 + chLoc] = v0;
                sbuf[(rloc + 8) * 20 + chLoc] = v1;
            }
        }
    }
    __syncthreads();
    {
        int row = tid >> 1, half = tid & 1;
        const float* s = &sbuf[row * 20 + half * 8];
        float4 o0 = make_float4(s[0], s[1], s[2], s[3]);
        float4 o1 = make_float4(s[4], s[5], s[6], s[7]);
        float* dst = &g_cmin[(size_t)(rowBase + row) * NCH + blockIdx.y * 16 + half * 8];
        reinterpret_cast<float4*>(dst)[0] = o0;
        reinterpret_cast<float4*>(dst)[1] = o1;
    }
}

// per-row exact rescore + gather + straight-through + rowsq. block=128, grid=N_ROWS
__global__ void rescore_kernel(const float* __restrict__ x,
                               const float* __restrict__ emb,
                               float* __restrict__ out) {
    const int row = blockIdx.x, tid = threadIdx.x;
    __shared__ __align__(16) float sx[DIM];
    __shared__ float sred[4];
    __shared__ unsigned sflags[32];
    __shared__ float scd[8];
    __shared__ int sidx;

    float4 xl = reinterpret_cast<const float4*>(x + (size_t)row * DIM)[tid];
    reinterpret_cast<float4*>(sx)[tid] = xl;
    if (tid < 32) sflags[tid] = 0;

    const float* cm = &g_cmin[(size_t)row * NCH];
    float cv[8];
    float lmin = 3.4028235e38f;
    #pragma unroll
    for (int q = 0; q < 8; q++) { cv[q] = cm[tid * 8 + q]; lmin = fminf(lmin, cv[q]); }
    #pragma unroll
    for (int off = 16; off; off >>= 1) lmin = fminf(lmin, __shfl_xor_sync(0xffffffffu, lmin, off));
    if ((tid & 31) == 0) sred[tid >> 5] = lmin;
    __syncthreads();
    float thr = fminf(fminf(sred[0], sred[1]), fminf(sred[2], sred[3])) + EPS;
    #pragma unroll
    for (int q = 0; q < 8; q++) {
        int ci = tid * 8 + q;
        if (cv[q] <= thr) atomicOr(&sflags[ci >> 5], 1u << (ci & 31));
    }
    __syncthreads();

    const float xn = g_xnorm[row];
    const int g = tid >> 4, l16 = tid & 15;
    float bestd = 3.4028235e38f;
    int besti = 0x7fffffff;

    for (int wdx = 0; wdx < 32; wdx++) {
        unsigned m = sflags[wdx];
        while (m) {
            int b = __ffs(m) - 1;
            m &= m - 1;
            int ci = wdx * 32 + b;
            int code = ci * 8 + g;
            const float4* e4 = reinterpret_cast<const float4*>(emb + (size_t)code * DIM);
            float acc = 0.f;
            #pragma unroll
            for (int q = 0; q < 8; q++) {
                float4 ev = e4[q * 16 + l16];
                float4 xv = reinterpret_cast<const float4*>(sx)[q * 16 + l16];
                acc = fmaf(ev.x, xv.x, acc);
                acc = fmaf(ev.y, xv.y, acc);
                acc = fmaf(ev.z, xv.z, acc);
                acc = fmaf(ev.w, xv.w, acc);
            }
            #pragma unroll
            for (int off = 8; off; off >>= 1) acc += __shfl_xor_sync(0xffffffffu, acc, off);
            if (l16 == 0)
                scd[g] = __fsub_rn(__fadd_rn(xn, g_enorm[code]), 2.0f * acc);
            __syncthreads();
            if (tid == 0) {
                #pragma unroll
                for (int gg = 0; gg < 8; gg++) {
                    float d = scd[gg];
                    int id = ci * 8 + gg;
                    if (d < bestd) { bestd = d; besti = id; }
                }
            }
            __syncthreads();
        }
    }

    if (tid == 0) {
        sidx = besti;
        out[Q_ELEMS + 2 + row] = (float)besti;
        atomicMax(&g_maxidx, besti);
    }
    __syncthreads();
    const int idx = sidx;

    float4 q4 = reinterpret_cast<const float4*>(emb + (size_t)idx * DIM)[tid];
    float4 xr = reinterpret_cast<const float4*>(sx)[tid];
    float4 o4;
    float ss = 0.f;
    {
        float d0 = __fsub_rn(q4.x, xr.x); o4.x = __fadd_rn(xr.x, d0); ss += d0 * d0;
        float d1 = __fsub_rn(q4.y, xr.y); o4.y = __fadd_rn(xr.y, d1); ss += d1 * d1;
        float d2 = __fsub_rn(q4.z, xr.z); o4.z = __fadd_rn(xr.z, d2); ss += d2 * d2;
        float d3 = __fsub_rn(q4.w, xr.w); o4.w = __fadd_rn(xr.w, d3); ss += d3 * d3;
    }
    reinterpret_cast<float4*>(out + (size_t)row * DIM)[tid] = o4;
    #pragma unroll
    for (int off = 16; off; off >>= 1) ss += __shfl_xor_sync(0xffffffffu, ss, off);
    __syncthreads();
    if ((tid & 31) == 0) sred[tid >> 5] = ss;
    __syncthreads();
    if (tid == 0) g_rowsq[row] = (sred[0] + sred[1]) + (sred[2] + sred[3]);
}

__global__ void scalars_kernel(float* __restrict__ out) {
    __shared__ float red[1024];
    const int tid = threadIdx.x;
    float s = 0.f;
    for (int r = tid; r < N_ROWS; r += 1024) s += g_rowsq[r];
    red[tid] = s;
    __syncthreads();
    #pragma unroll
    for (int st = 512; st > 0; st >>= 1) {
        if (tid < st) red[tid] += red[tid + st];
        __syncthreads();
    }
    if (tid == 0) {
        float mean = red[0] / (float)Q_ELEMS;
        out[Q_ELEMS] = 1.25f * mean;
        float L = (float)(g_maxidx + 1);
        float avg = 1.0f / L;
        out[Q_ELEMS + 1] = expf(-avg * logf(avg + 1e-10f));
    }
}

extern "C" void kernel_launch(void* const* d_in, const int* in_sizes, int n_in,
                              void* d_out, int out_size) {
    const float* x   = (const float*)d_in[0];
    const float* emb = (const float*)d_in[1];
    float* out = (float*)d_out;

    cudaFuncSetAttribute(vq_gemm_kernel, cudaFuncAttributeMaxDynamicSharedMemorySize, SM_TOTAL);

    init_kernel<<<1, 1>>>();
    convert_kernel<<<(N_ROWS + N_CODES) / 8, 256>>>(x, emb);
    vq_gemm_kernel<<<dim3(N_ROWS / BM, N_CODES / BN), 256, SM_TOTAL>>>();
    rescore_kernel<<<N_ROWS, 128>>>(x, emb, out);
    scalars_kernel<<<1, 1024>>>(out);
}